// round 1
// baseline (speedup 1.0000x reference)
#include <cuda_runtime.h>

#define C      128
#define TN     128
#define RS     132            // shared row stride (floats)
#define NTOT   16384
#define BATCH  16
#define NHEADS 8

__device__ float g_S[BATCH][NHEADS][16][16];
__device__ float g_Z[BATCH][C];
__device__ float g_G[BATCH][C][C];

// ---------------- packed f32x2 helpers (sm_103a) ----------------
__device__ __forceinline__ unsigned long long dup2(float w) {
    unsigned long long r;
    asm("mov.b64 %0, {%1, %1};" : "=l"(r) : "f"(w));
    return r;
}
__device__ __forceinline__ unsigned long long pack2(float a, float b) {
    unsigned long long r;
    asm("mov.b64 %0, {%1, %2};" : "=l"(r) : "f"(a), "f"(b));
    return r;
}
__device__ __forceinline__ void ffma2(unsigned long long& d, unsigned long long a, unsigned long long b) {
    asm("fma.rn.f32x2 %0, %1, %2, %0;" : "+l"(d) : "l"(a), "l"(b));
}
__device__ __forceinline__ float2 unpack2(unsigned long long v) {
    float2 r;
    asm("mov.b64 {%0, %1}, %2;" : "=f"(r.x), "=f"(r.y) : "l"(v));
    return r;
}

// 128x128x128 GEMM tile: 256 threads, each 8 rows x 8 cols.
// Rows: ty*8..+7.  Cols: {tx*4..+3, 64+tx*4..+3}  (conflict-free LDS.128).
__device__ __forceinline__ void gemm_tile(const float* __restrict__ sW,
                                          const float* __restrict__ sXv,
                                          unsigned long long acc[8][4],
                                          int ty, int tx) {
#pragma unroll 4
    for (int c = 0; c < C; c++) {
        const float4 w0 = *(const float4*)(sW + c * RS + ty * 8);
        const float4 w1 = *(const float4*)(sW + c * RS + ty * 8 + 4);
        const float4 x0 = *(const float4*)(sXv + c * RS + tx * 4);
        const float4 x1 = *(const float4*)(sXv + c * RS + 64 + tx * 4);
        unsigned long long xp0 = pack2(x0.x, x0.y);
        unsigned long long xp1 = pack2(x0.z, x0.w);
        unsigned long long xp2 = pack2(x1.x, x1.y);
        unsigned long long xp3 = pack2(x1.z, x1.w);
        float wv[8] = {w0.x, w0.y, w0.z, w0.w, w1.x, w1.y, w1.z, w1.w};
#pragma unroll
        for (int i = 0; i < 8; i++) {
            unsigned long long wd = dup2(wv[i]);
            ffma2(acc[i][0], wd, xp0);
            ffma2(acc[i][1], wd, xp1);
            ffma2(acc[i][2], wd, xp2);
            ffma2(acc[i][3], wd, xp3);
        }
    }
}

__device__ __forceinline__ void load_x_tile(float* sX, const float* xg, int t) {
    for (int idx = t; idx < C * (TN / 4); idx += 256) {
        int c = idx >> 5, j4 = (idx & 31) << 2;
        *(float4*)(sX + c * RS + j4) = *(const float4*)(xg + (size_t)c * NTOT + j4);
    }
}
__device__ __forceinline__ void load_wt(float* sWt, const float* __restrict__ W, int t) {
    // W: [128 rows][128 inner] row-major  ->  sWt[inner][row]
    for (int idx = t; idx < C * C; idx += 256) {
        int r = idx >> 7, c = idx & 127;
        sWt[c * RS + r] = W[idx];
    }
}

__global__ void zero_kernel() {
    int t = blockIdx.x * blockDim.x + threadIdx.x;
    float* S = &g_S[0][0][0][0];
    if (t < BATCH * NHEADS * 16 * 16) S[t] = 0.f;
    if (t < BATCH * C) (&g_Z[0][0])[t] = 0.f;
}

// ---------------- Pass A: exp(keys), values, accumulate S and Z ----------------
__global__ void __launch_bounds__(256, 1)
passA_kernel(const float* __restrict__ x, const float* __restrict__ Wk,
             const float* __restrict__ bk, const float* __restrict__ Wv,
             const float* __restrict__ bv) {
    extern __shared__ float sm[];
    float* sX  = sm;                // x tile, later values tile
    float* sWt = sm + C * RS;       // transposed weights
    float* sE  = sm + 2 * C * RS;   // exp(keys)
    const int t  = threadIdx.x;
    const int b  = blockIdx.y;
    const int n0 = blockIdx.x * TN;
    const float* xg = x + (size_t)b * C * NTOT + n0;

    load_x_tile(sX, xg, t);
    load_wt(sWt, Wk, t);
    __syncthreads();

    const int ty = t >> 4, tx = t & 15;
    unsigned long long acc[8][4];
#pragma unroll
    for (int i = 0; i < 8; i++)
#pragma unroll
        for (int j = 0; j < 4; j++) acc[i][j] = 0ULL;
    gemm_tile(sWt, sX, acc, ty, tx);

    // exp(keys + bk) -> sE
#pragma unroll
    for (int i = 0; i < 8; i++) {
        int row = ty * 8 + i;
        float bki = bk[row];
        float o[8];
#pragma unroll
        for (int j = 0; j < 4; j++) {
            float2 p = unpack2(acc[i][j]);
            o[2 * j]     = __expf(p.x + bki);
            o[2 * j + 1] = __expf(p.y + bki);
        }
        *(float4*)(sE + row * RS + tx * 4)      = make_float4(o[0], o[1], o[2], o[3]);
        *(float4*)(sE + row * RS + 64 + tx * 4) = make_float4(o[4], o[5], o[6], o[7]);
    }
    __syncthreads();   // all reads of sWt (Wk) done

    load_wt(sWt, Wv, t);
    __syncthreads();

#pragma unroll
    for (int i = 0; i < 8; i++)
#pragma unroll
        for (int j = 0; j < 4; j++) acc[i][j] = 0ULL;
    gemm_tile(sWt, sX, acc, ty, tx);
    __syncthreads();   // all reads of sX (x) done before overwrite

    // values (+bv) -> sX
#pragma unroll
    for (int i = 0; i < 8; i++) {
        int row = ty * 8 + i;
        float bvi = bv[row];
        float o[8];
#pragma unroll
        for (int j = 0; j < 4; j++) {
            float2 p = unpack2(acc[i][j]);
            o[2 * j]     = p.x + bvi;
            o[2 * j + 1] = p.y + bvi;
        }
        *(float4*)(sX + row * RS + tx * 4)      = make_float4(o[0], o[1], o[2], o[3]);
        *(float4*)(sX + row * RS + 64 + tx * 4) = make_float4(o[4], o[5], o[6], o[7]);
    }
    __syncthreads();

    // S[h][k][v] += sum_n e[k][n] * v[v][n];  Z[kc] += sum_n e[k][n]
    const int h  = t >> 5;          // warp = head
    const int l  = t & 31;
    const int k  = l & 15;
    const int vg = (l >> 4) << 3;   // 0 or 8
    const float* erow = sE + (h * 16 + k) * RS;
    float s[8];
#pragma unroll
    for (int j = 0; j < 8; j++) s[j] = 0.f;
    float zp = 0.f;
    for (int n = 0; n < TN; n += 4) {
        float4 e4 = *(const float4*)(erow + n);
        if (l < 16) zp += e4.x + e4.y + e4.z + e4.w;
#pragma unroll
        for (int j = 0; j < 8; j++) {
            float4 v4 = *(const float4*)(sX + (h * 16 + vg + j) * RS + n);
            s[j] += e4.x * v4.x + e4.y * v4.y + e4.z * v4.z + e4.w * v4.w;
        }
    }
#pragma unroll
    for (int j = 0; j < 8; j++) atomicAdd(&g_S[b][h][k][vg + j], s[j]);
    if (l < 16) atomicAdd(&g_Z[b][h * 16 + k], zp);
}

// ---------------- G[b][c][hk] = sum_v Wr[c][h*16+v] * S[b][h][k][v] / Z[b][hk] ----------------
__global__ void gctx_kernel(const float* __restrict__ Wr) {
    int b = blockIdx.x, cc = threadIdx.x;   // 128 threads
    for (int hk = 0; hk < C; hk++) {
        int h = hk >> 4, k = hk & 15;
        float a = 0.f;
#pragma unroll
        for (int v = 0; v < 16; v++)
            a += Wr[cc * C + h * 16 + v] * g_S[b][h][k][v];
        g_G[b][cc][hk] = a / g_Z[b][h * 16 + k];
    }
}

// ---------------- Pass B: queries, head-softmax, out = x + br + G @ qsm ----------------
__global__ void __launch_bounds__(256, 1)
passB_kernel(const float* __restrict__ x, const float* __restrict__ Wq,
             const float* __restrict__ bq, const float* __restrict__ br,
             float* __restrict__ out) {
    extern __shared__ float sm[];
    float* sX  = sm;
    float* sWt = sm + C * RS;
    float* sQ  = sm + 2 * C * RS;
    const int t  = threadIdx.x;
    const int b  = blockIdx.y;
    const int n0 = blockIdx.x * TN;
    const float* xg = x + (size_t)b * C * NTOT + n0;

    load_x_tile(sX, xg, t);
    load_wt(sWt, Wq, t);
    __syncthreads();

    const int ty = t >> 4, tx = t & 15;
    unsigned long long acc[8][4];
#pragma unroll
    for (int i = 0; i < 8; i++)
#pragma unroll
        for (int j = 0; j < 4; j++) acc[i][j] = 0ULL;
    gemm_tile(sWt, sX, acc, ty, tx);

    // queries + bq -> sQ
#pragma unroll
    for (int i = 0; i < 8; i++) {
        int row = ty * 8 + i;
        float bqi = bq[row];
        float o[8];
#pragma unroll
        for (int j = 0; j < 4; j++) {
            float2 p = unpack2(acc[i][j]);
            o[2 * j]     = p.x + bqi;
            o[2 * j + 1] = p.y + bqi;
        }
        *(float4*)(sQ + row * RS + tx * 4)      = make_float4(o[0], o[1], o[2], o[3]);
        *(float4*)(sQ + row * RS + 64 + tx * 4) = make_float4(o[4], o[5], o[6], o[7]);
    }
    __syncthreads();

    // per-(head, pixel) softmax over 16 channels, in place in sQ
    for (int g = t; g < NHEADS * TN; g += 256) {
        int n = g & (TN - 1), h = g >> 7;
        float v[16], m = -1e30f;
#pragma unroll
        for (int kk = 0; kk < 16; kk++) {
            v[kk] = sQ[(h * 16 + kk) * RS + n];
            m = fmaxf(m, v[kk]);
        }
        float ssum = 0.f;
#pragma unroll
        for (int kk = 0; kk < 16; kk++) { v[kk] = __expf(v[kk] - m); ssum += v[kk]; }
        float inv = 1.f / ssum;
#pragma unroll
        for (int kk = 0; kk < 16; kk++) sQ[(h * 16 + kk) * RS + n] = v[kk] * inv;
    }
    __syncthreads();

    load_wt(sWt, &g_G[b][0][0], t);   // G[b][c][qc] -> sWt[qc][c]
    __syncthreads();

#pragma unroll
    for (int i = 0; i < 8; i++)
#pragma unroll
        for (int j = 0; j < 4; j++) acc[i][j] = 0ULL;
    gemm_tile(sWt, sQ, acc, ty, tx);

    float* og = out + (size_t)b * C * NTOT + n0;
#pragma unroll
    for (int i = 0; i < 8; i++) {
        int row = ty * 8 + i;
        float bri = br[row];
        const float* xr = sX + row * RS;
        float o[8];
#pragma unroll
        for (int j = 0; j < 4; j++) {
            float2 p = unpack2(acc[i][j]);
            o[2 * j]     = p.x + bri;
            o[2 * j + 1] = p.y + bri;
        }
        float4 r0 = make_float4(o[0] + xr[tx * 4],     o[1] + xr[tx * 4 + 1],
                                o[2] + xr[tx * 4 + 2], o[3] + xr[tx * 4 + 3]);
        float4 r1 = make_float4(o[4] + xr[64 + tx * 4],     o[5] + xr[64 + tx * 4 + 1],
                                o[6] + xr[64 + tx * 4 + 2], o[7] + xr[64 + tx * 4 + 3]);
        *(float4*)(og + (size_t)row * NTOT + tx * 4)      = r0;
        *(float4*)(og + (size_t)row * NTOT + 64 + tx * 4) = r1;
    }
}

extern "C" void kernel_launch(void* const* d_in, const int* in_sizes, int n_in,
                              void* d_out, int out_size) {
    const float* x  = (const float*)d_in[0];
    const float* Wk = (const float*)d_in[1];
    const float* bk = (const float*)d_in[2];
    const float* Wq = (const float*)d_in[3];
    const float* bq = (const float*)d_in[4];
    const float* Wv = (const float*)d_in[5];
    const float* bv = (const float*)d_in[6];
    const float* Wr = (const float*)d_in[7];
    const float* br = (const float*)d_in[8];
    float* out = (float*)d_out;

    const int smem = 3 * C * RS * (int)sizeof(float);   // 202,752 B
    cudaFuncSetAttribute(passA_kernel, cudaFuncAttributeMaxDynamicSharedMemorySize, smem);
    cudaFuncSetAttribute(passB_kernel, cudaFuncAttributeMaxDynamicSharedMemorySize, smem);

    zero_kernel<<<128, 256>>>();
    passA_kernel<<<dim3(NTOT / TN, BATCH), 256, smem>>>(x, Wk, bk, Wv, bv);
    gctx_kernel<<<BATCH, 128>>>(Wr);
    passB_kernel<<<dim3(NTOT / TN, BATCH), 256, smem>>>(x, Wq, bq, br, out);
}

// round 3
// speedup vs baseline: 2.1532x; 2.1532x over previous
#include <cuda_runtime.h>
#include <cstdint>

#define C      128
#define NTOT   16384
#define BATCH  16
#define NHEADS 8
#define RS     132     // smem row stride (floats): bank = (4*row + col) % 32

__device__ float g_S[BATCH][NHEADS][16][16];
__device__ float g_Z[BATCH][C];
__device__ float g_G[BATCH][C][C];

// ---------------- tf32 mma.sync (legacy path, compiles for sm_103) ----------------
__device__ __forceinline__ void mma_tf32(float d[4], const uint32_t a[4], const uint32_t b[2]) {
    asm volatile(
        "mma.sync.aligned.m16n8k8.row.col.f32.tf32.tf32.f32 "
        "{%0,%1,%2,%3}, {%4,%5,%6,%7}, {%8,%9}, {%0,%1,%2,%3};"
        : "+f"(d[0]), "+f"(d[1]), "+f"(d[2]), "+f"(d[3])
        : "r"(a[0]), "r"(a[1]), "r"(a[2]), "r"(a[3]), "r"(b[0]), "r"(b[1]));
}

// fast exp on FMA pipe (no MUFU): 2^(x*log2e), deg-4 poly, rel err ~6e-5
__device__ __forceinline__ float fexp(float x) {
    float y = x * 1.4426950408889634f;
    float r = rintf(y);
    float f = y - r;
    float p = 0.0096181291f;
    p = fmaf(p, f, 0.0555041086f);
    p = fmaf(p, f, 0.2402265069f);
    p = fmaf(p, f, 0.6931471806f);
    p = fmaf(p, f, 1.0f);
    int i = (int)r;
    return __int_as_float(__float_as_int(p) + (i << 23));
}

// D[128][128] = A[128rows][128k] (row-major, stride RS) x B, with B[n][k] (stride RS).
// 8 warps: wm=w&3 -> 32-row band, wn=w>>2 -> 64-col band. acc[2 mtiles][8 ntiles][4].
__device__ __forceinline__ void gemm128(const float* __restrict__ sA,
                                        const float* __restrict__ sB,
                                        float acc[2][8][4], int g, int tig, int rm, int cn) {
#pragma unroll 4
    for (int kb = 0; kb < 16; kb++) {
        const int k0 = kb * 8;
        uint32_t a[2][4], bf[8][2];
#pragma unroll
        for (int mt = 0; mt < 2; mt++) {
            const float* ap = sA + (rm + mt * 16 + g) * RS + k0;
            a[mt][0] = __float_as_uint(ap[tig]);
            a[mt][1] = __float_as_uint(ap[8 * RS + tig]);
            a[mt][2] = __float_as_uint(ap[tig + 4]);
            a[mt][3] = __float_as_uint(ap[8 * RS + tig + 4]);
        }
#pragma unroll
        for (int nt = 0; nt < 8; nt++) {
            const float* bp = sB + (cn + nt * 8 + g) * RS + k0;
            bf[nt][0] = __float_as_uint(bp[tig]);
            bf[nt][1] = __float_as_uint(bp[tig + 4]);
        }
#pragma unroll
        for (int nt = 0; nt < 8; nt++) {
            mma_tf32(acc[0][nt], a[0], bf[nt]);
            mma_tf32(acc[1][nt], a[1], bf[nt]);
        }
    }
}

// transpose-load x tile: gmem [c][n] -> sXT[n][c]; conflict-free STS.128
__device__ __forceinline__ void load_xT(float* sXT, const float* __restrict__ xg, int l, int w) {
    const int c0 = l * 4;
#pragma unroll
    for (int i = 0; i < 4; i++) {
        int n0 = (i * 8 + w) * 4;
        const float* base = xg + (size_t)c0 * NTOT + n0;
        float4 r0 = *(const float4*)(base);
        float4 r1 = *(const float4*)(base + NTOT);
        float4 r2 = *(const float4*)(base + 2 * NTOT);
        float4 r3 = *(const float4*)(base + 3 * NTOT);
        *(float4*)(sXT + (n0 + 0) * RS + c0) = make_float4(r0.x, r1.x, r2.x, r3.x);
        *(float4*)(sXT + (n0 + 1) * RS + c0) = make_float4(r0.y, r1.y, r2.y, r3.y);
        *(float4*)(sXT + (n0 + 2) * RS + c0) = make_float4(r0.z, r1.z, r2.z, r3.z);
        *(float4*)(sXT + (n0 + 3) * RS + c0) = make_float4(r0.w, r1.w, r2.w, r3.w);
    }
}

__device__ __forceinline__ void load_w(float* sW, const float* __restrict__ W, int t) {
#pragma unroll
    for (int i = 0; i < 16; i++) {
        int idx = i * 256 + t;
        int m = idx >> 5, k4 = (idx & 31) * 4;
        *(float4*)(sW + m * RS + k4) = *(const float4*)(W + m * C + k4);
    }
}

__global__ void zero_kernel() {
    int t = blockIdx.x * blockDim.x + threadIdx.x;
    if (t < BATCH * NHEADS * 16 * 16) (&g_S[0][0][0][0])[t] = 0.f;
    if (t < BATCH * C) (&g_Z[0][0])[t] = 0.f;
}

// ================= Pass A: E=exp(Wk x+bk), V=Wv x+bv, S+=E V^T (diag), Z+=rowsum(E) ===============
__global__ void __launch_bounds__(256, 1)
passA_kernel(const float* __restrict__ x, const float* __restrict__ Wk,
             const float* __restrict__ bk, const float* __restrict__ Wv,
             const float* __restrict__ bv) {
    extern __shared__ float sm[];
    float* sXT = sm;                 // [n][c], later reused as V [vc][n]
    float* sW  = sm + 128 * RS;
    float* sE  = sm + 2 * 128 * RS;  // [kc][n]

    const int t = threadIdx.x, l = t & 31, w = t >> 5;
    const int g = l >> 2, tig = l & 3;
    const int rm = (w & 3) * 32, cn = (w >> 2) * 64;
    const int b = blockIdx.y;
    const float* xg = x + (size_t)b * C * NTOT + blockIdx.x * 128;

    load_xT(sXT, xg, l, w);
    load_w(sW, Wk, t);
    __syncthreads();

    float acc[2][8][4];
#pragma unroll
    for (int mt = 0; mt < 2; mt++)
#pragma unroll
        for (int nt = 0; nt < 8; nt++)
#pragma unroll
            for (int j = 0; j < 4; j++) acc[mt][nt][j] = 0.f;
    gemm128(sW, sXT, acc, g, tig, rm, cn);

    // exp -> sE, accumulate row sums z
    float zs[2][2] = {{0.f, 0.f}, {0.f, 0.f}};
#pragma unroll
    for (int mt = 0; mt < 2; mt++) {
        int r0 = rm + mt * 16 + g;
        float b0 = bk[r0], b1 = bk[r0 + 8];
#pragma unroll
        for (int nt = 0; nt < 8; nt++) {
            int n0 = cn + nt * 8 + tig * 2;
            float e0 = fexp(acc[mt][nt][0] + b0);
            float e1 = fexp(acc[mt][nt][1] + b0);
            float e2 = fexp(acc[mt][nt][2] + b1);
            float e3 = fexp(acc[mt][nt][3] + b1);
            zs[mt][0] += e0 + e1;
            zs[mt][1] += e2 + e3;
            *(float2*)(sE + r0 * RS + n0)       = make_float2(e0, e1);
            *(float2*)(sE + (r0 + 8) * RS + n0) = make_float2(e2, e3);
        }
    }
#pragma unroll
    for (int mt = 0; mt < 2; mt++)
#pragma unroll
        for (int h = 0; h < 2; h++) {
            float z = zs[mt][h];
            z += __shfl_xor_sync(0xffffffffu, z, 1);
            z += __shfl_xor_sync(0xffffffffu, z, 2);
            if (tig == 0) atomicAdd(&g_Z[b][rm + mt * 16 + h * 8 + g], z);
        }

    __syncthreads();
    load_w(sW, Wv, t);
    __syncthreads();

#pragma unroll
    for (int mt = 0; mt < 2; mt++)
#pragma unroll
        for (int nt = 0; nt < 8; nt++)
#pragma unroll
            for (int j = 0; j < 4; j++) acc[mt][nt][j] = 0.f;
    gemm128(sW, sXT, acc, g, tig, rm, cn);
    __syncthreads();              // all reads of sXT done; reuse as V [vc][n]

#pragma unroll
    for (int mt = 0; mt < 2; mt++) {
        int r0 = rm + mt * 16 + g;
        float b0 = bv[r0], b1 = bv[r0 + 8];
#pragma unroll
        for (int nt = 0; nt < 8; nt++) {
            int n0 = cn + nt * 8 + tig * 2;
            *(float2*)(sXT + r0 * RS + n0)       = make_float2(acc[mt][nt][0] + b0, acc[mt][nt][1] + b0);
            *(float2*)(sXT + (r0 + 8) * RS + n0) = make_float2(acc[mt][nt][2] + b1, acc[mt][nt][3] + b1);
        }
    }
    __syncthreads();

    // S GEMM: D[kc][vc] = sum_n E[kc][n] * V[vc][n]; keep block-diagonal
#pragma unroll
    for (int mt = 0; mt < 2; mt++)
#pragma unroll
        for (int nt = 0; nt < 8; nt++)
#pragma unroll
            for (int j = 0; j < 4; j++) acc[mt][nt][j] = 0.f;
    gemm128(sE, sXT, acc, g, tig, rm, cn);

    float* Sb = &g_S[b][0][0][0];
#pragma unroll
    for (int mt = 0; mt < 2; mt++) {
        int r0 = rm + mt * 16 + g, r1 = r0 + 8;
#pragma unroll
        for (int nt = 0; nt < 8; nt++) {
            int c0 = cn + nt * 8 + tig * 2;
            if ((r0 >> 4) == (c0 >> 4)) {
                atomicAdd(Sb + (r0 >> 4) * 256 + (r0 & 15) * 16 + (c0 & 15),       acc[mt][nt][0]);
                atomicAdd(Sb + (r0 >> 4) * 256 + (r0 & 15) * 16 + ((c0 + 1) & 15), acc[mt][nt][1]);
            }
            if ((r1 >> 4) == (c0 >> 4)) {
                atomicAdd(Sb + (r1 >> 4) * 256 + (r1 & 15) * 16 + (c0 & 15),       acc[mt][nt][2]);
                atomicAdd(Sb + (r1 >> 4) * 256 + (r1 & 15) * 16 + ((c0 + 1) & 15), acc[mt][nt][3]);
            }
        }
    }
}

// ---- G[b][c][hk] = sum_v Wr[c][h*16+v] * S[b][h][k][v] / Z[b][hk] ----
__global__ void gctx_kernel(const float* __restrict__ Wr) {
    int b = blockIdx.x, cc = threadIdx.x;
    for (int hk = 0; hk < C; hk++) {
        int h = hk >> 4, k = hk & 15;
        float a = 0.f;
#pragma unroll
        for (int v = 0; v < 16; v++)
            a += Wr[cc * C + h * 16 + v] * g_S[b][h][k][v];
        g_G[b][cc][hk] = a / g_Z[b][h * 16 + k];
    }
}

// ================= Pass B: q=softmax_head(Wq x+bq); out = x + br + G q =================
__global__ void __launch_bounds__(256, 1)
passB_kernel(const float* __restrict__ x, const float* __restrict__ Wq,
             const float* __restrict__ bq, const float* __restrict__ br,
             float* __restrict__ out) {
    extern __shared__ float sm[];
    float* sXT = sm;                 // [n][c]
    float* sW  = sm + 128 * RS;
    float* sQ  = sm + 2 * 128 * RS;  // [n][kq]

    const int t = threadIdx.x, l = t & 31, w = t >> 5;
    const int g = l >> 2, tig = l & 3;
    const int rm = (w & 3) * 32, cn = (w >> 2) * 64;
    const int b = blockIdx.y;
    const int n0g = blockIdx.x * 128;
    const float* xg = x + (size_t)b * C * NTOT + n0g;

    load_xT(sXT, xg, l, w);
    load_w(sW, Wq, t);
    __syncthreads();

    float acc[2][8][4];
#pragma unroll
    for (int mt = 0; mt < 2; mt++)
#pragma unroll
        for (int nt = 0; nt < 8; nt++)
#pragma unroll
            for (int j = 0; j < 4; j++) acc[mt][nt][j] = 0.f;
    gemm128(sW, sXT, acc, g, tig, rm, cn);

    // scatter q + bq -> sQ[n][kq]  (conflict-free STS.32)
#pragma unroll
    for (int mt = 0; mt < 2; mt++) {
        int r0 = rm + mt * 16 + g;
        float b0 = bq[r0], b1 = bq[r0 + 8];
#pragma unroll
        for (int nt = 0; nt < 8; nt++) {
            int n0 = cn + nt * 8 + tig * 2;
            sQ[(n0) * RS + r0]         = acc[mt][nt][0] + b0;
            sQ[(n0 + 1) * RS + r0]     = acc[mt][nt][1] + b0;
            sQ[(n0) * RS + r0 + 8]     = acc[mt][nt][2] + b1;
            sQ[(n0 + 1) * RS + r0 + 8] = acc[mt][nt][3] + b1;
        }
    }
    __syncthreads();

    load_w(sW, &g_G[b][0][0], t);   // overlap G load with softmax

    // softmax over 16 kq per (h, n); no max-subtract needed (|q| small)
#pragma unroll
    for (int i = 0; i < 4; i++) {
        int p = i * 256 + t;
        int n = p & 127, h = p >> 7;
        float* qp = sQ + n * RS + h * 16;
        float4 v0 = *(float4*)(qp);
        float4 v1 = *(float4*)(qp + 4);
        float4 v2 = *(float4*)(qp + 8);
        float4 v3 = *(float4*)(qp + 12);
        v0.x = fexp(v0.x); v0.y = fexp(v0.y); v0.z = fexp(v0.z); v0.w = fexp(v0.w);
        v1.x = fexp(v1.x); v1.y = fexp(v1.y); v1.z = fexp(v1.z); v1.w = fexp(v1.w);
        v2.x = fexp(v2.x); v2.y = fexp(v2.y); v2.z = fexp(v2.z); v2.w = fexp(v2.w);
        v3.x = fexp(v3.x); v3.y = fexp(v3.y); v3.z = fexp(v3.z); v3.w = fexp(v3.w);
        float s = (v0.x + v0.y + v0.z + v0.w) + (v1.x + v1.y + v1.z + v1.w)
                + (v2.x + v2.y + v2.z + v2.w) + (v3.x + v3.y + v3.z + v3.w);
        float inv = 1.0f / s;
        v0.x *= inv; v0.y *= inv; v0.z *= inv; v0.w *= inv;
        v1.x *= inv; v1.y *= inv; v1.z *= inv; v1.w *= inv;
        v2.x *= inv; v2.y *= inv; v2.z *= inv; v2.w *= inv;
        v3.x *= inv; v3.y *= inv; v3.z *= inv; v3.w *= inv;
        *(float4*)(qp)      = v0;
        *(float4*)(qp + 4)  = v1;
        *(float4*)(qp + 8)  = v2;
        *(float4*)(qp + 12) = v3;
    }
    __syncthreads();

    // out GEMM: D[c][n] = G[c][kq] * qsm  (B = sQ[n][kq])
#pragma unroll
    for (int mt = 0; mt < 2; mt++)
#pragma unroll
        for (int nt = 0; nt < 8; nt++)
#pragma unroll
            for (int j = 0; j < 4; j++) acc[mt][nt][j] = 0.f;
    gemm128(sW, sQ, acc, g, tig, rm, cn);

    // store: out = D + x + br
#pragma unroll
    for (int mt = 0; mt < 2; mt++) {
        int r0 = rm + mt * 16 + g;
        float b0 = br[r0], b1 = br[r0 + 8];
        const float* xr0 = x + ((size_t)b * C + r0) * NTOT + n0g;
        const float* xr1 = xr0 + 8 * NTOT;
        float* o0 = out + ((size_t)b * C + r0) * NTOT + n0g;
        float* o1 = o0 + 8 * NTOT;
#pragma unroll
        for (int nt = 0; nt < 8; nt++) {
            int n0 = cn + nt * 8 + tig * 2;
            float2 xa = *(const float2*)(xr0 + n0);
            float2 xb = *(const float2*)(xr1 + n0);
            *(float2*)(o0 + n0) = make_float2(acc[mt][nt][0] + b0 + xa.x, acc[mt][nt][1] + b0 + xa.y);
            *(float2*)(o1 + n0) = make_float2(acc[mt][nt][2] + b1 + xb.x, acc[mt][nt][3] + b1 + xb.y);
        }
    }
}

extern "C" void kernel_launch(void* const* d_in, const int* in_sizes, int n_in,
                              void* d_out, int out_size) {
    const float* x  = (const float*)d_in[0];
    const float* Wk = (const float*)d_in[1];
    const float* bk = (const float*)d_in[2];
    const float* Wq = (const float*)d_in[3];
    const float* bq = (const float*)d_in[4];
    const float* Wv = (const float*)d_in[5];
    const float* bv = (const float*)d_in[6];
    const float* Wr = (const float*)d_in[7];
    const float* br = (const float*)d_in[8];
    float* out = (float*)d_out;

    const int smem = 3 * 128 * RS * (int)sizeof(float);   // 202,752 B
    cudaFuncSetAttribute(passA_kernel, cudaFuncAttributeMaxDynamicSharedMemorySize, smem);
    cudaFuncSetAttribute(passB_kernel, cudaFuncAttributeMaxDynamicSharedMemorySize, smem);

    zero_kernel<<<128, 256>>>();
    passA_kernel<<<dim3(NTOT / 128, BATCH), 256, smem>>>(x, Wk, bk, Wv, bv);
    gctx_kernel<<<BATCH, 128>>>(Wr);
    passB_kernel<<<dim3(NTOT / 128, BATCH), 256, smem>>>(x, Wq, bq, br, out);
}

// round 4
// speedup vs baseline: 2.8574x; 1.3270x over previous
#include <cuda_runtime.h>
#include <cuda_bf16.h>
#include <cstdint>

#define C      128
#define NTOT   16384
#define BATCH  16
#define NHEADS 8
#define KSB    272      // bytes per smem row: 136 bf16 (128 data + 8 pad)
#define BUF    34816    // 128 rows * 272 B
#define SMEMT  (3 * BUF)

__device__ float g_S[BATCH][NHEADS][16][16];
__device__ float g_Z[BATCH][C];
__device__ float g_G[BATCH][C][C];

// ---------------- mma / ldmatrix ----------------
__device__ __forceinline__ void mma_bf16(float d[4], const uint32_t a[4], uint32_t b0, uint32_t b1) {
    asm volatile(
        "mma.sync.aligned.m16n8k16.row.col.f32.bf16.bf16.f32 "
        "{%0,%1,%2,%3}, {%4,%5,%6,%7}, {%8,%9}, {%0,%1,%2,%3};"
        : "+f"(d[0]), "+f"(d[1]), "+f"(d[2]), "+f"(d[3])
        : "r"(a[0]), "r"(a[1]), "r"(a[2]), "r"(a[3]), "r"(b0), "r"(b1));
}
__device__ __forceinline__ void ldsm4(uint32_t r[4], uint32_t addr) {
    asm volatile("ldmatrix.sync.aligned.m8n8.x4.shared.b16 {%0,%1,%2,%3}, [%4];"
                 : "=r"(r[0]), "=r"(r[1]), "=r"(r[2]), "=r"(r[3]) : "r"(addr));
}
__device__ __forceinline__ uint32_t packbf(float lo, float hi) {
    __nv_bfloat162 h = __floats2bfloat162_rn(lo, hi);
    return *(uint32_t*)&h;
}
// fast exp on FMA pipe: 2^(x*log2e), deg-4 poly
__device__ __forceinline__ float fexp(float x) {
    float y = x * 1.4426950408889634f;
    float r = rintf(y);
    float f = y - r;
    float p = 0.0096181291f;
    p = fmaf(p, f, 0.0555041086f);
    p = fmaf(p, f, 0.2402265069f);
    p = fmaf(p, f, 0.6931471806f);
    p = fmaf(p, f, 1.0f);
    return __int_as_float(__float_as_int(p) + ((int)r << 23));
}

// D[128][128] = A[128 rows][128 k] x B[128 n][128 k], bf16 operands (row stride KSB), f32 acc.
// 8 warps: (w&3) -> 32-row band, (w>>2) -> 64-col band. k-steps of 16, ldmatrix.x4 operands.
__device__ __forceinline__ void gemm128b(uint32_t aAb, uint32_t aBb, float acc[2][8][4],
                                         int lane, int rm, int cn) {
    const int m = lane >> 3, lr = lane & 7;
    const uint32_t aA0 = aAb + (uint32_t)(rm + (m & 1) * 8 + lr) * KSB + (m >> 1) * 16;
    const uint32_t aB0 = aBb + (uint32_t)(cn + (m >> 1) * 8 + lr) * KSB + (m & 1) * 16;
#pragma unroll
    for (int kb = 0; kb < 8; kb++) {
        uint32_t a[2][4], b[4][4];
        ldsm4(a[0], aA0 + kb * 32);
        ldsm4(a[1], aA0 + 16 * KSB + kb * 32);
#pragma unroll
        for (int p = 0; p < 4; p++) ldsm4(b[p], aB0 + p * 16 * KSB + kb * 32);
#pragma unroll
        for (int p = 0; p < 4; p++) {
            mma_bf16(acc[0][2 * p],     a[0], b[p][0], b[p][1]);
            mma_bf16(acc[0][2 * p + 1], a[0], b[p][2], b[p][3]);
            mma_bf16(acc[1][2 * p],     a[1], b[p][0], b[p][1]);
            mma_bf16(acc[1][2 * p + 1], a[1], b[p][2], b[p][3]);
        }
    }
}

// transpose-load x tile: gmem [c][n] f32 -> s [n][c] bf16
__device__ __forceinline__ void load_xT(char* s, const float* __restrict__ xg, int l, int w) {
    const int c0 = l * 4;
#pragma unroll
    for (int i = 0; i < 4; i++) {
        int n0 = (i * 8 + w) * 4;
        const float* base = xg + (size_t)c0 * NTOT + n0;
        float4 r0 = *(const float4*)(base);
        float4 r1 = *(const float4*)(base + NTOT);
        float4 r2 = *(const float4*)(base + 2 * NTOT);
        float4 r3 = *(const float4*)(base + 3 * NTOT);
        uint2 p0 = make_uint2(packbf(r0.x, r1.x), packbf(r2.x, r3.x));
        uint2 p1 = make_uint2(packbf(r0.y, r1.y), packbf(r2.y, r3.y));
        uint2 p2 = make_uint2(packbf(r0.z, r1.z), packbf(r2.z, r3.z));
        uint2 p3 = make_uint2(packbf(r0.w, r1.w), packbf(r2.w, r3.w));
        *(uint2*)(s + (n0 + 0) * KSB + c0 * 2) = p0;
        *(uint2*)(s + (n0 + 1) * KSB + c0 * 2) = p1;
        *(uint2*)(s + (n0 + 2) * KSB + c0 * 2) = p2;
        *(uint2*)(s + (n0 + 3) * KSB + c0 * 2) = p3;
    }
}
// load 128x128 f32 row-major matrix -> bf16 smem (stride KSB)
__device__ __forceinline__ void load_w(char* s, const float* __restrict__ W, int t) {
#pragma unroll
    for (int i = 0; i < 16; i++) {
        int idx = i * 256 + t;
        int m = idx >> 5, k4 = (idx & 31) * 4;
        float4 v = *(const float4*)(W + m * C + k4);
        *(uint2*)(s + m * KSB + k4 * 2) = make_uint2(packbf(v.x, v.y), packbf(v.z, v.w));
    }
}

__global__ void zero_kernel() {
    int t = blockIdx.x * blockDim.x + threadIdx.x;
    if (t < BATCH * NHEADS * 16 * 16) (&g_S[0][0][0][0])[t] = 0.f;
    if (t < BATCH * C) (&g_Z[0][0])[t] = 0.f;
}

// ================= Pass A =================
__global__ void __launch_bounds__(256, 2)
passA_kernel(const float* __restrict__ x, const float* __restrict__ Wk,
             const float* __restrict__ bk, const float* __restrict__ Wv,
             const float* __restrict__ bv) {
    extern __shared__ char sm[];
    char* sB = sm;              // x^T [n][c], later V [vc][n]
    char* sW = sm + BUF;        // Wk then Wv
    char* sE = sm + 2 * BUF;    // E [kc][n]
    const uint32_t sBa = (uint32_t)__cvta_generic_to_shared(sB);
    const uint32_t sWa = (uint32_t)__cvta_generic_to_shared(sW);
    const uint32_t sEa = (uint32_t)__cvta_generic_to_shared(sE);

    const int t = threadIdx.x, l = t & 31, w = t >> 5;
    const int g = l >> 2, tig = l & 3;
    const int rm = (w & 3) * 32, cn = (w >> 2) * 64;
    const int b = blockIdx.y;
    const float* xg = x + (size_t)b * C * NTOT + blockIdx.x * 128;

    load_xT(sB, xg, l, w);
    load_w(sW, Wk, t);
    __syncthreads();

    float acc[2][8][4];
#pragma unroll
    for (int mt = 0; mt < 2; mt++)
#pragma unroll
        for (int nt = 0; nt < 8; nt++)
#pragma unroll
            for (int j = 0; j < 4; j++) acc[mt][nt][j] = 0.f;
    gemm128b(sWa, sBa, acc, l, rm, cn);

    // exp(keys + bk) -> sE (bf16), row sums -> g_Z
    float zs[2][2] = {{0.f, 0.f}, {0.f, 0.f}};
#pragma unroll
    for (int mt = 0; mt < 2; mt++) {
        int r0 = rm + mt * 16 + g;
        float b0 = bk[r0], b1 = bk[r0 + 8];
#pragma unroll
        for (int nt = 0; nt < 8; nt++) {
            int n0 = cn + nt * 8 + tig * 2;
            float e0 = fexp(acc[mt][nt][0] + b0);
            float e1 = fexp(acc[mt][nt][1] + b0);
            float e2 = fexp(acc[mt][nt][2] + b1);
            float e3 = fexp(acc[mt][nt][3] + b1);
            zs[mt][0] += e0 + e1;
            zs[mt][1] += e2 + e3;
            *(uint32_t*)(sE + r0 * KSB + n0 * 2)       = packbf(e0, e1);
            *(uint32_t*)(sE + (r0 + 8) * KSB + n0 * 2) = packbf(e2, e3);
        }
    }
#pragma unroll
    for (int mt = 0; mt < 2; mt++)
#pragma unroll
        for (int h = 0; h < 2; h++) {
            float z = zs[mt][h];
            z += __shfl_xor_sync(0xffffffffu, z, 1);
            z += __shfl_xor_sync(0xffffffffu, z, 2);
            if (tig == 0) atomicAdd(&g_Z[b][rm + mt * 16 + h * 8 + g], z);
        }

    __syncthreads();            // all reads of sW (Wk) complete
    load_w(sW, Wv, t);
    __syncthreads();

#pragma unroll
    for (int mt = 0; mt < 2; mt++)
#pragma unroll
        for (int nt = 0; nt < 8; nt++)
#pragma unroll
            for (int j = 0; j < 4; j++) acc[mt][nt][j] = 0.f;
    gemm128b(sWa, sBa, acc, l, rm, cn);
    __syncthreads();            // all reads of sB (x^T) done; reuse as V [vc][n]

#pragma unroll
    for (int mt = 0; mt < 2; mt++) {
        int r0 = rm + mt * 16 + g;
        float b0 = bv[r0], b1 = bv[r0 + 8];
#pragma unroll
        for (int nt = 0; nt < 8; nt++) {
            int n0 = cn + nt * 8 + tig * 2;
            *(uint32_t*)(sB + r0 * KSB + n0 * 2)       = packbf(acc[mt][nt][0] + b0, acc[mt][nt][1] + b0);
            *(uint32_t*)(sB + (r0 + 8) * KSB + n0 * 2) = packbf(acc[mt][nt][2] + b1, acc[mt][nt][3] + b1);
        }
    }
    __syncthreads();

    // S GEMM: D[kc][vc] = sum_n E[kc][n] * V[vc][n]; keep block-diagonal
#pragma unroll
    for (int mt = 0; mt < 2; mt++)
#pragma unroll
        for (int nt = 0; nt < 8; nt++)
#pragma unroll
            for (int j = 0; j < 4; j++) acc[mt][nt][j] = 0.f;
    gemm128b(sEa, sBa, acc, l, rm, cn);

    float* Sb = &g_S[b][0][0][0];
#pragma unroll
    for (int mt = 0; mt < 2; mt++) {
        int r0 = rm + mt * 16 + g, r1 = r0 + 8;
#pragma unroll
        for (int nt = 0; nt < 8; nt++) {
            int c0 = cn + nt * 8 + tig * 2;
            if ((r0 >> 4) == (c0 >> 4)) {
                atomicAdd(Sb + (r0 >> 4) * 256 + (r0 & 15) * 16 + (c0 & 15),       acc[mt][nt][0]);
                atomicAdd(Sb + (r0 >> 4) * 256 + (r0 & 15) * 16 + ((c0 + 1) & 15), acc[mt][nt][1]);
            }
            if ((r1 >> 4) == (c0 >> 4)) {
                atomicAdd(Sb + (r1 >> 4) * 256 + (r1 & 15) * 16 + (c0 & 15),       acc[mt][nt][2]);
                atomicAdd(Sb + (r1 >> 4) * 256 + (r1 & 15) * 16 + ((c0 + 1) & 15), acc[mt][nt][3]);
            }
        }
    }
}

// ---- G[b][c][hk] = sum_v Wr[c][h*16+v] * S[b][h][k][v] / Z[b][hk] ----
__global__ void gctx_kernel(const float* __restrict__ Wr) {
    int b = blockIdx.x, cc = threadIdx.x;
    for (int hk = 0; hk < C; hk++) {
        int h = hk >> 4, k = hk & 15;
        float a = 0.f;
#pragma unroll
        for (int v = 0; v < 16; v++)
            a += Wr[cc * C + h * 16 + v] * g_S[b][h][k][v];
        g_G[b][cc][hk] = a / g_Z[b][h * 16 + k];
    }
}

// ================= Pass B =================
__global__ void __launch_bounds__(256, 2)
passB_kernel(const float* __restrict__ x, const float* __restrict__ Wq,
             const float* __restrict__ bq, const float* __restrict__ br,
             float* __restrict__ out) {
    extern __shared__ char sm[];
    char* sB = sm;              // x^T [n][c]
    char* sW = sm + BUF;        // Wq then G
    char* sQ = sm + 2 * BUF;    // q [n][kq]
    const uint32_t sBa = (uint32_t)__cvta_generic_to_shared(sB);
    const uint32_t sWa = (uint32_t)__cvta_generic_to_shared(sW);
    const uint32_t sQa = (uint32_t)__cvta_generic_to_shared(sQ);

    const int t = threadIdx.x, l = t & 31, w = t >> 5;
    const int g = l >> 2, tig = l & 3;
    const int rm = (w & 3) * 32, cn = (w >> 2) * 64;
    const int b = blockIdx.y;
    const int n0g = blockIdx.x * 128;
    const float* xg = x + (size_t)b * C * NTOT + n0g;

    load_xT(sB, xg, l, w);
    load_w(sW, Wq, t);
    __syncthreads();

    float acc[2][8][4];
#pragma unroll
    for (int mt = 0; mt < 2; mt++)
#pragma unroll
        for (int nt = 0; nt < 8; nt++)
#pragma unroll
            for (int j = 0; j < 4; j++) acc[mt][nt][j] = 0.f;
    gemm128b(sWa, sBa, acc, l, rm, cn);

    // scatter q + bq -> sQ[n][kq] (bf16 u16 stores)
#pragma unroll
    for (int mt = 0; mt < 2; mt++) {
        int r0 = rm + mt * 16 + g;
        float b0 = bq[r0], b1 = bq[r0 + 8];
#pragma unroll
        for (int nt = 0; nt < 8; nt++) {
            int n0 = cn + nt * 8 + tig * 2;
            *(__nv_bfloat16*)(sQ + (n0) * KSB + r0 * 2)           = __float2bfloat16_rn(acc[mt][nt][0] + b0);
            *(__nv_bfloat16*)(sQ + (n0 + 1) * KSB + r0 * 2)       = __float2bfloat16_rn(acc[mt][nt][1] + b0);
            *(__nv_bfloat16*)(sQ + (n0) * KSB + (r0 + 8) * 2)     = __float2bfloat16_rn(acc[mt][nt][2] + b1);
            *(__nv_bfloat16*)(sQ + (n0 + 1) * KSB + (r0 + 8) * 2) = __float2bfloat16_rn(acc[mt][nt][3] + b1);
        }
    }
    __syncthreads();            // q written; GEMM1's sW reads done

    load_w(sW, &g_G[b][0][0], t);   // overlap with softmax

    // softmax over 16 kq per (h, n), in-place bf16
#pragma unroll
    for (int i = 0; i < 4; i++) {
        int p = i * 256 + t;
        int n = p & 127, h = p >> 7;
        char* qp = sQ + n * KSB + h * 32;
        uint4 u0 = *(uint4*)(qp);
        uint4 u1 = *(uint4*)(qp + 16);
        float v[16];
        {
            float2 f;
            f = __bfloat1622float2(*(__nv_bfloat162*)&u0.x); v[0] = f.x;  v[1] = f.y;
            f = __bfloat1622float2(*(__nv_bfloat162*)&u0.y); v[2] = f.x;  v[3] = f.y;
            f = __bfloat1622float2(*(__nv_bfloat162*)&u0.z); v[4] = f.x;  v[5] = f.y;
            f = __bfloat1622float2(*(__nv_bfloat162*)&u0.w); v[6] = f.x;  v[7] = f.y;
            f = __bfloat1622float2(*(__nv_bfloat162*)&u1.x); v[8] = f.x;  v[9] = f.y;
            f = __bfloat1622float2(*(__nv_bfloat162*)&u1.y); v[10] = f.x; v[11] = f.y;
            f = __bfloat1622float2(*(__nv_bfloat162*)&u1.z); v[12] = f.x; v[13] = f.y;
            f = __bfloat1622float2(*(__nv_bfloat162*)&u1.w); v[14] = f.x; v[15] = f.y;
        }
        float s = 0.f;
#pragma unroll
        for (int kk = 0; kk < 16; kk++) { v[kk] = fexp(v[kk]); s += v[kk]; }
        float inv = 1.0f / s;
        u0.x = packbf(v[0] * inv,  v[1] * inv);
        u0.y = packbf(v[2] * inv,  v[3] * inv);
        u0.z = packbf(v[4] * inv,  v[5] * inv);
        u0.w = packbf(v[6] * inv,  v[7] * inv);
        u1.x = packbf(v[8] * inv,  v[9] * inv);
        u1.y = packbf(v[10] * inv, v[11] * inv);
        u1.z = packbf(v[12] * inv, v[13] * inv);
        u1.w = packbf(v[14] * inv, v[15] * inv);
        *(uint4*)(qp)      = u0;
        *(uint4*)(qp + 16) = u1;
    }
    __syncthreads();

    // out GEMM: D[c][n] = G[c][kq] * q[n][kq]
#pragma unroll
    for (int mt = 0; mt < 2; mt++)
#pragma unroll
        for (int nt = 0; nt < 8; nt++)
#pragma unroll
            for (int j = 0; j < 4; j++) acc[mt][nt][j] = 0.f;
    gemm128b(sWa, sQa, acc, l, rm, cn);

    // store: out = D + br + x (f32 residual re-read)
#pragma unroll
    for (int mt = 0; mt < 2; mt++) {
        int r0 = rm + mt * 16 + g;
        float b0 = br[r0], b1 = br[r0 + 8];
        const float* xr0 = x + ((size_t)b * C + r0) * NTOT + n0g;
        const float* xr1 = xr0 + 8 * NTOT;
        float* o0 = out + ((size_t)b * C + r0) * NTOT + n0g;
        float* o1 = o0 + 8 * NTOT;
#pragma unroll
        for (int nt = 0; nt < 8; nt++) {
            int n0 = cn + nt * 8 + tig * 2;
            float2 xa = *(const float2*)(xr0 + n0);
            float2 xb = *(const float2*)(xr1 + n0);
            *(float2*)(o0 + n0) = make_float2(acc[mt][nt][0] + b0 + xa.x, acc[mt][nt][1] + b0 + xa.y);
            *(float2*)(o1 + n0) = make_float2(acc[mt][nt][2] + b1 + xb.x, acc[mt][nt][3] + b1 + xb.y);
        }
    }
}

extern "C" void kernel_launch(void* const* d_in, const int* in_sizes, int n_in,
                              void* d_out, int out_size) {
    const float* x  = (const float*)d_in[0];
    const float* Wk = (const float*)d_in[1];
    const float* bk = (const float*)d_in[2];
    const float* Wq = (const float*)d_in[3];
    const float* bq = (const float*)d_in[4];
    const float* Wv = (const float*)d_in[5];
    const float* bv = (const float*)d_in[6];
    const float* Wr = (const float*)d_in[7];
    const float* br = (const float*)d_in[8];
    float* out = (float*)d_out;

    cudaFuncSetAttribute(passA_kernel, cudaFuncAttributeMaxDynamicSharedMemorySize, SMEMT);
    cudaFuncSetAttribute(passB_kernel, cudaFuncAttributeMaxDynamicSharedMemorySize, SMEMT);

    zero_kernel<<<128, 256>>>();
    passA_kernel<<<dim3(NTOT / 128, BATCH), 256, SMEMT>>>(x, Wk, bk, Wv, bv);
    gctx_kernel<<<BATCH, 128>>>(Wr);
    passB_kernel<<<dim3(NTOT / 128, BATCH), 256, SMEMT>>>(x, Wq, bq, br, out);
}

// round 5
// speedup vs baseline: 2.9369x; 1.0278x over previous
#include <cuda_runtime.h>
#include <cuda_bf16.h>
#include <cstdint>

#define C      128
#define NTOT   16384
#define BATCH  16
#define KSB    272      // smem row stride bytes (128 bf16 + 8 pad)
#define BUF    34816    // 128 * KSB
#define BPB    9        // blocks per batch
#define NTILE  128      // 128-pixel tiles per batch

__device__ float g_S[BATCH][8][16][16];
__device__ float g_Z[BATCH][C];
__device__ float g_G[BATCH][C][C];

// ---------------- primitives ----------------
__device__ __forceinline__ void mma_bf16(float d[4], const uint32_t a[4], uint32_t b0, uint32_t b1) {
    asm volatile(
        "mma.sync.aligned.m16n8k16.row.col.f32.bf16.bf16.f32 "
        "{%0,%1,%2,%3}, {%4,%5,%6,%7}, {%8,%9}, {%0,%1,%2,%3};"
        : "+f"(d[0]), "+f"(d[1]), "+f"(d[2]), "+f"(d[3])
        : "r"(a[0]), "r"(a[1]), "r"(a[2]), "r"(a[3]), "r"(b0), "r"(b1));
}
__device__ __forceinline__ void ldsm4(uint32_t r[4], uint32_t addr) {
    asm volatile("ldmatrix.sync.aligned.m8n8.x4.shared.b16 {%0,%1,%2,%3}, [%4];"
                 : "=r"(r[0]), "=r"(r[1]), "=r"(r[2]), "=r"(r[3]) : "r"(addr));
}
__device__ __forceinline__ uint32_t packbf(float lo, float hi) {
    __nv_bfloat162 h = __floats2bfloat162_rn(lo, hi);
    return *(uint32_t*)&h;
}
__device__ __forceinline__ float fexp(float x) {   // FMA-pipe exp
    float y = x * 1.4426950408889634f;
    float r = rintf(y);
    float f = y - r;
    float p = 0.0096181291f;
    p = fmaf(p, f, 0.0555041086f);
    p = fmaf(p, f, 0.2402265069f);
    p = fmaf(p, f, 0.6931471806f);
    p = fmaf(p, f, 1.0f);
    return __int_as_float(__float_as_int(p) + ((int)r << 23));
}

// 32x32 warp tile of a 128x128x128 GEMM; 16 warps (4x4). acc[2 mtiles][4 ntiles][4].
__device__ __forceinline__ void gemm_warp(uint32_t aA, uint32_t aB, float acc[2][4][4],
                                          int lane, int rm, int cn) {
    const int m = lane >> 3, lr = lane & 7;
    const uint32_t aA0 = aA + (uint32_t)(rm + (m & 1) * 8 + lr) * KSB + (m >> 1) * 16;
    const uint32_t aB0 = aB + (uint32_t)(cn + (m >> 1) * 8 + lr) * KSB + (m & 1) * 16;
#pragma unroll
    for (int kb = 0; kb < 8; kb++) {
        uint32_t a[2][4], b[2][4];
        ldsm4(a[0], aA0 + kb * 32);
        ldsm4(a[1], aA0 + 16 * KSB + kb * 32);
        ldsm4(b[0], aB0 + kb * 32);
        ldsm4(b[1], aB0 + 16 * KSB + kb * 32);
#pragma unroll
        for (int mt = 0; mt < 2; mt++)
#pragma unroll
            for (int p = 0; p < 2; p++) {
                mma_bf16(acc[mt][2 * p],     a[mt], b[p][0], b[p][1]);
                mma_bf16(acc[mt][2 * p + 1], a[mt], b[p][2], b[p][3]);
            }
    }
}

// transpose-load x tile: gmem [c][n] f32 -> smem [n][c] bf16 (512 threads)
__device__ __forceinline__ void load_xT(char* s, const float* __restrict__ xg, int t) {
    const int c0 = (t & 31) * 4;
    const int nb = (t >> 5) * 8;
#pragma unroll
    for (int i = 0; i < 2; i++) {
        int n0 = nb + i * 4;
        const float* base = xg + (size_t)c0 * NTOT + n0;
        float4 r0 = *(const float4*)(base);
        float4 r1 = *(const float4*)(base + NTOT);
        float4 r2 = *(const float4*)(base + 2 * NTOT);
        float4 r3 = *(const float4*)(base + 3 * NTOT);
        *(uint2*)(s + (n0 + 0) * KSB + c0 * 2) = make_uint2(packbf(r0.x, r1.x), packbf(r2.x, r3.x));
        *(uint2*)(s + (n0 + 1) * KSB + c0 * 2) = make_uint2(packbf(r0.y, r1.y), packbf(r2.y, r3.y));
        *(uint2*)(s + (n0 + 2) * KSB + c0 * 2) = make_uint2(packbf(r0.z, r1.z), packbf(r2.z, r3.z));
        *(uint2*)(s + (n0 + 3) * KSB + c0 * 2) = make_uint2(packbf(r0.w, r1.w), packbf(r2.w, r3.w));
    }
}
// load 128x128 f32 row-major -> bf16 smem (512 threads)
__device__ __forceinline__ void load_w(char* s, const float* __restrict__ W, int t) {
#pragma unroll
    for (int i = 0; i < 8; i++) {
        int idx = i * 512 + t;
        int mm = idx >> 5, k4 = (idx & 31) * 4;
        float4 v = *(const float4*)(W + mm * C + k4);
        *(uint2*)(s + mm * KSB + k4 * 2) = make_uint2(packbf(v.x, v.y), packbf(v.z, v.w));
    }
}

__global__ void zero_kernel() {
    int t = blockIdx.x * blockDim.x + threadIdx.x;
    if (t < BATCH * 8 * 16 * 16) (&g_S[0][0][0][0])[t] = 0.f;
    if (t < BATCH * C) (&g_Z[0][0])[t] = 0.f;
}

// ================= Pass A =================
__global__ void __launch_bounds__(512, 1)
passA_kernel(const float* __restrict__ x, const float* __restrict__ Wk,
             const float* __restrict__ bk, const float* __restrict__ Wv,
             const float* __restrict__ bv) {
    extern __shared__ char sm[];
    char* sWk = sm;
    char* sWv = sm + BUF;
    char* sV  = sm + 2 * BUF;
    char* sB0 = sm + 3 * BUF;
    char* sB1 = sm + 4 * BUF;
    const uint32_t aWk = (uint32_t)__cvta_generic_to_shared(sWk);
    const uint32_t aWv = (uint32_t)__cvta_generic_to_shared(sWv);
    const uint32_t aV  = (uint32_t)__cvta_generic_to_shared(sV);
    const uint32_t aB[2] = {(uint32_t)__cvta_generic_to_shared(sB0),
                            (uint32_t)__cvta_generic_to_shared(sB1)};
    char* pB[2] = {sB0, sB1};

    const int t = threadIdx.x, l = t & 31, w = t >> 5;
    const int g = l >> 2, tig = l & 3, m = l >> 3, lr = l & 7;
    const int rm = (w & 3) * 32, cn = (w >> 2) * 32;
    const int b = blockIdx.y;
    const float* xb = x + (size_t)b * C * NTOT;

    load_w(sWk, Wk, t);
    load_w(sWv, Wv, t);
    int tt = blockIdx.x;
    load_xT(pB[0], xb + tt * 128, t);
    __syncthreads();

    float bk0[2], bk1[2], bv0[2], bv1[2];
#pragma unroll
    for (int mt = 0; mt < 2; mt++) {
        bk0[mt] = bk[rm + mt * 16 + g];     bk1[mt] = bk[rm + mt * 16 + 8 + g];
        bv0[mt] = bv[rm + mt * 16 + g];     bv1[mt] = bv[rm + mt * 16 + 8 + g];
    }

    float accS[2][2][4];
    float zacc[2][2] = {{0.f, 0.f}, {0.f, 0.f}};
#pragma unroll
    for (int mt = 0; mt < 2; mt++)
#pragma unroll
        for (int p = 0; p < 2; p++)
#pragma unroll
            for (int j = 0; j < 4; j++) accS[mt][p][j] = 0.f;

    int cur = 0;
    for (; tt < NTILE; tt += BPB) {
        const int nxt = tt + BPB;
        float acc[2][4][4];
#pragma unroll
        for (int mt = 0; mt < 2; mt++)
#pragma unroll
            for (int nt = 0; nt < 4; nt++)
#pragma unroll
                for (int j = 0; j < 4; j++) acc[mt][nt][j] = 0.f;
        gemm_warp(aWk, aB[cur], acc, l, rm, cn);

        // exp(keys+bk) -> A fragments for S-MMA (registers only) + Z partial sums
        uint32_t ef[2][2][4];
#pragma unroll
        for (int mt = 0; mt < 2; mt++)
#pragma unroll
            for (int kc = 0; kc < 2; kc++) {
                float e00 = fexp(acc[mt][2 * kc][0] + bk0[mt]);
                float e01 = fexp(acc[mt][2 * kc][1] + bk0[mt]);
                float e10 = fexp(acc[mt][2 * kc][2] + bk1[mt]);
                float e11 = fexp(acc[mt][2 * kc][3] + bk1[mt]);
                float e20 = fexp(acc[mt][2 * kc + 1][0] + bk0[mt]);
                float e21 = fexp(acc[mt][2 * kc + 1][1] + bk0[mt]);
                float e30 = fexp(acc[mt][2 * kc + 1][2] + bk1[mt]);
                float e31 = fexp(acc[mt][2 * kc + 1][3] + bk1[mt]);
                zacc[mt][0] += (e00 + e01) + (e20 + e21);
                zacc[mt][1] += (e10 + e11) + (e30 + e31);
                ef[mt][kc][0] = packbf(e00, e01);   // row g,   k<8
                ef[mt][kc][1] = packbf(e10, e11);   // row g+8, k<8
                ef[mt][kc][2] = packbf(e20, e21);   // row g,   k>=8
                ef[mt][kc][3] = packbf(e30, e31);   // row g+8, k>=8
            }

        // values GEMM
#pragma unroll
        for (int mt = 0; mt < 2; mt++)
#pragma unroll
            for (int nt = 0; nt < 4; nt++)
#pragma unroll
                for (int j = 0; j < 4; j++) acc[mt][nt][j] = 0.f;
        gemm_warp(aWv, aB[cur], acc, l, rm, cn);

        // scatter V+bv -> sV [vc][n] (conflict-free u32 stores)
#pragma unroll
        for (int mt = 0; mt < 2; mt++) {
            int r0 = rm + mt * 16 + g;
#pragma unroll
            for (int nt = 0; nt < 4; nt++) {
                int n0 = cn + nt * 8 + tig * 2;
                *(uint32_t*)(sV + r0 * KSB + n0 * 2)       = packbf(acc[mt][nt][0] + bv0[mt], acc[mt][nt][1] + bv0[mt]);
                *(uint32_t*)(sV + (r0 + 8) * KSB + n0 * 2) = packbf(acc[mt][nt][2] + bv1[mt], acc[mt][nt][3] + bv1[mt]);
            }
        }
        if (nxt < NTILE) load_xT(pB[cur ^ 1], xb + nxt * 128, t);
        __syncthreads();

        // S-MMA: head h = rm/16 + mt, k over this warp's 32 pixels
#pragma unroll
        for (int mt = 0; mt < 2; mt++) {
            const int h = (rm >> 4) + mt;
#pragma unroll
            for (int kc = 0; kc < 2; kc++) {
                uint32_t bS[4];
                ldsm4(bS, aV + (uint32_t)(h * 16 + (m >> 1) * 8 + lr) * KSB
                             + (m & 1) * 16 + (cn + kc * 16) * 2);
                mma_bf16(accS[mt][0], ef[mt][kc], bS[0], bS[1]);
                mma_bf16(accS[mt][1], ef[mt][kc], bS[2], bS[3]);
            }
        }
        cur ^= 1;
        __syncthreads();
    }

    // flush S and Z
#pragma unroll
    for (int mt = 0; mt < 2; mt++) {
        const int h = (rm >> 4) + mt;
#pragma unroll
        for (int p = 0; p < 2; p++) {
            atomicAdd(&g_S[b][h][g][p * 8 + 2 * tig],         accS[mt][p][0]);
            atomicAdd(&g_S[b][h][g][p * 8 + 2 * tig + 1],     accS[mt][p][1]);
            atomicAdd(&g_S[b][h][g + 8][p * 8 + 2 * tig],     accS[mt][p][2]);
            atomicAdd(&g_S[b][h][g + 8][p * 8 + 2 * tig + 1], accS[mt][p][3]);
        }
    }
#pragma unroll
    for (int mt = 0; mt < 2; mt++)
#pragma unroll
        for (int half = 0; half < 2; half++) {
            float z = zacc[mt][half];
            z += __shfl_xor_sync(0xffffffffu, z, 1);
            z += __shfl_xor_sync(0xffffffffu, z, 2);
            if (tig == 0) atomicAdd(&g_Z[b][rm + mt * 16 + half * 8 + g], z);
        }
}

// ---- G[b][c][hk] = sum_v Wr[c][h*16+v] * S[b][h][k][v] / Z[b][hk] ----
__global__ void gctx_kernel(const float* __restrict__ Wr) {
    int b = blockIdx.x, cc = threadIdx.x;
    for (int hk = 0; hk < C; hk++) {
        int h = hk >> 4, k = hk & 15;
        float a = 0.f;
#pragma unroll
        for (int v = 0; v < 16; v++)
            a += Wr[cc * C + h * 16 + v] * g_S[b][h][k][v];
        g_G[b][cc][hk] = a / g_Z[b][h * 16 + k];
    }
}

// ================= Pass B =================
__global__ void __launch_bounds__(512, 1)
passB_kernel(const float* __restrict__ x, const float* __restrict__ Wq,
             const float* __restrict__ bq, const float* __restrict__ br,
             float* __restrict__ out) {
    extern __shared__ char sm[];
    char* sWq = sm;
    char* sG  = sm + BUF;
    char* sQ  = sm + 2 * BUF;
    char* sB0 = sm + 3 * BUF;
    char* sB1 = sm + 4 * BUF;
    const uint32_t aWq = (uint32_t)__cvta_generic_to_shared(sWq);
    const uint32_t aG  = (uint32_t)__cvta_generic_to_shared(sG);
    const uint32_t aQ  = (uint32_t)__cvta_generic_to_shared(sQ);
    const uint32_t aB[2] = {(uint32_t)__cvta_generic_to_shared(sB0),
                            (uint32_t)__cvta_generic_to_shared(sB1)};
    char* pB[2] = {sB0, sB1};

    const int t = threadIdx.x, l = t & 31, w = t >> 5;
    const int g = l >> 2, tig = l & 3;
    const int rm = (w & 3) * 32, cn = (w >> 2) * 32;
    const int b = blockIdx.y;
    const float* xb = x + (size_t)b * C * NTOT;
    float* ob = out + (size_t)b * C * NTOT;

    load_w(sWq, Wq, t);
    load_w(sG, &g_G[b][0][0], t);
    int tt = blockIdx.x;
    load_xT(pB[0], xb + tt * 128, t);
    __syncthreads();

    float bq0[2], bq1[2], br0[2], br1[2];
#pragma unroll
    for (int mt = 0; mt < 2; mt++) {
        bq0[mt] = bq[rm + mt * 16 + g];     bq1[mt] = bq[rm + mt * 16 + 8 + g];
        br0[mt] = br[rm + mt * 16 + g];     br1[mt] = br[rm + mt * 16 + 8 + g];
    }

    int cur = 0;
    for (; tt < NTILE; tt += BPB) {
        const int nxt = tt + BPB;
        float acc[2][4][4];
#pragma unroll
        for (int mt = 0; mt < 2; mt++)
#pragma unroll
            for (int nt = 0; nt < 4; nt++)
#pragma unroll
                for (int j = 0; j < 4; j++) acc[mt][nt][j] = 0.f;
        gemm_warp(aWq, aB[cur], acc, l, rm, cn);

        // softmax over 16 kq per (head, pixel), entirely in registers.
        // head rows live in this warp's mtile: rows {g, g+8} + shfl over g-lanes.
#pragma unroll
        for (int mt = 0; mt < 2; mt++) {
            int r0 = rm + mt * 16 + g;
#pragma unroll
            for (int nt = 0; nt < 4; nt++) {
                float e0 = fexp(acc[mt][nt][0] + bq0[mt]);
                float e1 = fexp(acc[mt][nt][1] + bq0[mt]);
                float e2 = fexp(acc[mt][nt][2] + bq1[mt]);
                float e3 = fexp(acc[mt][nt][3] + bq1[mt]);
                float s0 = e0 + e2;           // pixel n0 (col 2tig)
                float s1 = e1 + e3;           // pixel n0+1
                s0 += __shfl_xor_sync(0xffffffffu, s0, 4);
                s1 += __shfl_xor_sync(0xffffffffu, s1, 4);
                s0 += __shfl_xor_sync(0xffffffffu, s0, 8);
                s1 += __shfl_xor_sync(0xffffffffu, s1, 8);
                s0 += __shfl_xor_sync(0xffffffffu, s0, 16);
                s1 += __shfl_xor_sync(0xffffffffu, s1, 16);
                float i0 = 1.f / s0, i1 = 1.f / s1;
                int n0 = cn + nt * 8 + tig * 2;
                *(__nv_bfloat16*)(sQ + n0 * KSB + r0 * 2)             = __float2bfloat16_rn(e0 * i0);
                *(__nv_bfloat16*)(sQ + n0 * KSB + (r0 + 8) * 2)       = __float2bfloat16_rn(e2 * i0);
                *(__nv_bfloat16*)(sQ + (n0 + 1) * KSB + r0 * 2)       = __float2bfloat16_rn(e1 * i1);
                *(__nv_bfloat16*)(sQ + (n0 + 1) * KSB + (r0 + 8) * 2) = __float2bfloat16_rn(e3 * i1);
            }
        }
        if (nxt < NTILE) load_xT(pB[cur ^ 1], xb + nxt * 128, t);
        __syncthreads();

        // out GEMM: D[c][n] = G[c][kq] * q[n][kq]
#pragma unroll
        for (int mt = 0; mt < 2; mt++)
#pragma unroll
            for (int nt = 0; nt < 4; nt++)
#pragma unroll
                for (int j = 0; j < 4; j++) acc[mt][nt][j] = 0.f;
        gemm_warp(aG, aQ, acc, l, rm, cn);

        // epilogue: out = D + br + x (f32 residual)
#pragma unroll
        for (int mt = 0; mt < 2; mt++) {
            int r0 = rm + mt * 16 + g;
            const float* x0 = xb + (size_t)r0 * NTOT + tt * 128;
            const float* x1 = x0 + 8 * NTOT;
            float* o0 = ob + (size_t)r0 * NTOT + tt * 128;
            float* o1 = o0 + 8 * NTOT;
#pragma unroll
            for (int nt = 0; nt < 4; nt++) {
                int n0 = cn + nt * 8 + tig * 2;
                float2 xa = *(const float2*)(x0 + n0);
                float2 xc = *(const float2*)(x1 + n0);
                *(float2*)(o0 + n0) = make_float2(acc[mt][nt][0] + br0[mt] + xa.x,
                                                  acc[mt][nt][1] + br0[mt] + xa.y);
                *(float2*)(o1 + n0) = make_float2(acc[mt][nt][2] + br1[mt] + xc.x,
                                                  acc[mt][nt][3] + br1[mt] + xc.y);
            }
        }
        cur ^= 1;
        __syncthreads();
    }
}

extern "C" void kernel_launch(void* const* d_in, const int* in_sizes, int n_in,
                              void* d_out, int out_size) {
    const float* x  = (const float*)d_in[0];
    const float* Wk = (const float*)d_in[1];
    const float* bk = (const float*)d_in[2];
    const float* Wq = (const float*)d_in[3];
    const float* bq = (const float*)d_in[4];
    const float* Wv = (const float*)d_in[5];
    const float* bv = (const float*)d_in[6];
    const float* Wr = (const float*)d_in[7];
    const float* br = (const float*)d_in[8];
    float* out = (float*)d_out;

    const int smem = 5 * BUF;   // 174,080 B
    cudaFuncSetAttribute(passA_kernel, cudaFuncAttributeMaxDynamicSharedMemorySize, smem);
    cudaFuncSetAttribute(passB_kernel, cudaFuncAttributeMaxDynamicSharedMemorySize, smem);

    zero_kernel<<<128, 256>>>();
    passA_kernel<<<dim3(BPB, BATCH), 512, smem>>>(x, Wk, bk, Wv, bv);
    gctx_kernel<<<BATCH, 128>>>(Wr);
    passB_kernel<<<dim3(BPB, BATCH), 512, smem>>>(x, Wq, bq, br, out);
}